// round 2
// baseline (speedup 1.0000x reference)
#include <cuda_runtime.h>
#include <math.h>

// Problem constants (fixed shapes)
#define E_TOTAL 65536     // B*N*K = 2*1024*32
#define MIDW    256
#define W3OFF   768       // SPLIT_OFF = 256*3
#define RPN     768       // SPLIT_SZ = NF*MI*MO = 3*16*16

// Scratch (device globals; no runtime allocation allowed)
__device__ float g_H1[E_TOTAL * MIDW];        //  64 MB
__device__ float g_H2[E_TOTAL * MIDW];        //  64 MB
__device__ float g_RP[(size_t)E_TOTAL * RPN]; // 201 MB

__device__ __forceinline__ float gelu_exact(float x) {
    return 0.5f * x * (1.0f + erff(x * 0.70710678118654752440f));
}

// ---------------------------------------------------------------------------
// GEMM layer: C[row, n] = act(A[E,KTOT] @ B[KTOT, 256-chunk] (+ bias))
// Block: 64 rows x 256 cols, 256 threads, 8x8 thread tile, double-buffered.
// B has row stride ldb (1536 for the W3 slice), C has row stride ldc.
// ---------------------------------------------------------------------------
template<int KTOT, bool GELU>
__global__ __launch_bounds__(256, 2)
void mlp_gemm_kernel(const float* __restrict__ A, const float* __restrict__ B,
                     int ldb, const float* __restrict__ bias,
                     float* __restrict__ C, int ldc)
{
    __shared__ __align__(16) float sA[2][16][68];   // [k][m], padded
    __shared__ __align__(16) float sB[2][16][256];  // [k][n]

    const int tid = threadIdx.x;
    const int tx  = tid & 31;         // 32 col-threads
    const int ty  = tid >> 5;         // 8  row-threads
    const int row0 = blockIdx.x * 64;
    const int cb   = blockIdx.y;      // 256-col chunk index
    const int la_row = tid >> 2;      // 0..63  (A loader)
    const int la_seg = tid & 3;       // 0..3
    constexpr int NT = KTOT / 16;

    const float* Bc = B + (size_t)cb * 256;   // column chunk base

    float acc[8][8];
#pragma unroll
    for (int i = 0; i < 8; i++)
#pragma unroll
        for (int j = 0; j < 8; j++) acc[i][j] = 0.f;

    const float* Arow = A + (size_t)(row0 + la_row) * KTOT + la_seg * 4;

    // ---- load tile 0 ----
    float4 pa = *(const float4*)(Arow);
    float4 pb[4];
#pragma unroll
    for (int i = 0; i < 4; i++) {
        int f = tid + i * 256;            // float4 index in 16x256 tile
        int r = f >> 6, c4 = f & 63;
        pb[i] = *(const float4*)&Bc[(size_t)r * ldb + c4 * 4];
    }
    sA[0][la_seg*4+0][la_row] = pa.x;
    sA[0][la_seg*4+1][la_row] = pa.y;
    sA[0][la_seg*4+2][la_row] = pa.z;
    sA[0][la_seg*4+3][la_row] = pa.w;
#pragma unroll
    for (int i = 0; i < 4; i++) {
        int f = tid + i * 256;
        int r = f >> 6, c4 = f & 63;
        *(float4*)&sB[0][r][c4*4] = pb[i];
    }
    __syncthreads();

    int cur = 0;
#pragma unroll 1
    for (int kt = 0; kt < NT; kt++) {
        if (kt + 1 < NT) {
            pa = *(const float4*)(Arow + (kt + 1) * 16);
#pragma unroll
            for (int i = 0; i < 4; i++) {
                int f = tid + i * 256;
                int r = f >> 6, c4 = f & 63;
                pb[i] = *(const float4*)&Bc[(size_t)((kt + 1) * 16 + r) * ldb + c4 * 4];
            }
        }
#pragma unroll
        for (int k = 0; k < 16; k++) {
            float4 a0 = *(const float4*)&sA[cur][k][ty * 8];
            float4 a1 = *(const float4*)&sA[cur][k][ty * 8 + 4];
            float4 b0 = *(const float4*)&sB[cur][k][tx * 4];
            float4 b1 = *(const float4*)&sB[cur][k][128 + tx * 4];
            float av[8] = {a0.x, a0.y, a0.z, a0.w, a1.x, a1.y, a1.z, a1.w};
            float bv[8] = {b0.x, b0.y, b0.z, b0.w, b1.x, b1.y, b1.z, b1.w};
#pragma unroll
            for (int i = 0; i < 8; i++)
#pragma unroll
                for (int j = 0; j < 8; j++)
                    acc[i][j] = fmaf(av[i], bv[j], acc[i][j]);
        }
        if (kt + 1 < NT) {
            int nxt = cur ^ 1;
            sA[nxt][la_seg*4+0][la_row] = pa.x;
            sA[nxt][la_seg*4+1][la_row] = pa.y;
            sA[nxt][la_seg*4+2][la_row] = pa.z;
            sA[nxt][la_seg*4+3][la_row] = pa.w;
#pragma unroll
            for (int i = 0; i < 4; i++) {
                int f = tid + i * 256;
                int r = f >> 6, c4 = f & 63;
                *(float4*)&sB[nxt][r][c4*4] = pb[i];
            }
            __syncthreads();
            cur = nxt;
        }
    }

    // ---- epilogue ----
    float bb[8];
#pragma unroll
    for (int g = 0; g < 2; g++)
#pragma unroll
        for (int j = 0; j < 4; j++)
            bb[g*4+j] = bias ? bias[cb * 256 + g * 128 + tx * 4 + j] : 0.f;

#pragma unroll
    for (int i = 0; i < 8; i++) {
        size_t gr = (size_t)(row0 + ty * 8 + i);
        float* Crow = C + gr * ldc + cb * 256;
#pragma unroll
        for (int g = 0; g < 2; g++) {
            float4 v;
            float x0 = acc[i][g*4+0] + bb[g*4+0];
            float x1 = acc[i][g*4+1] + bb[g*4+1];
            float x2 = acc[i][g*4+2] + bb[g*4+2];
            float x3 = acc[i][g*4+3] + bb[g*4+3];
            if (GELU) {
                v.x = gelu_exact(x0); v.y = gelu_exact(x1);
                v.z = gelu_exact(x2); v.w = gelu_exact(x3);
            } else {
                v.x = x0; v.y = x1; v.z = x2; v.w = x3;
            }
            *(float4*)&Crow[g * 128 + tx * 4] = v;
        }
    }
}

// ---------------------------------------------------------------------------
// Tail: per edge e,
//   tmp[j= i*3+n][dd] = sum_d f[i,d] * basis[d, n*3+dd]       (48 x 3)
//   out[o][dd]        = sum_j RP[e, o*48 + j] * tmp[j][dd]    (16 x 3)
// Block = 16 edges x 16 threads (one thread per (edge, o)).
// ---------------------------------------------------------------------------
__global__ __launch_bounds__(256)
void tail_kernel(const float* __restrict__ RP, const float* __restrict__ feats,
                 const float* __restrict__ basis, float* __restrict__ out)
{
    __shared__ float sT[16][145];   // tmp, row-padded (145 mod 32 = 17)
    __shared__ float sF[16][48];
    __shared__ float sBA[16][27];

    const int tid = threadIdx.x;
    const int el  = tid >> 4;                  // edge within block
    const int o   = tid & 15;                  // output row
    const size_t e = (size_t)blockIdx.x * 16 + el;

    // stage feats (48/edge) and basis (27/edge)
    const float* fe = feats + e * 48;
    sF[el][o*3+0] = fe[o*3+0];
    sF[el][o*3+1] = fe[o*3+1];
    sF[el][o*3+2] = fe[o*3+2];
    const float* be = basis + e * 27;
    for (int idx = o; idx < 27; idx += 16) sBA[el][idx] = be[idx];
    __syncthreads();

    // tmp: thread handles j = o, o+16, o+32
#pragma unroll
    for (int jj = 0; jj < 3; jj++) {
        int j = o + jj * 16;
        int i = j / 3, n = j - i * 3;
        float f0 = sF[el][i*3+0], f1 = sF[el][i*3+1], f2 = sF[el][i*3+2];
#pragma unroll
        for (int dd = 0; dd < 3; dd++) {
            float v = f0 * sBA[el][0*9 + n*3 + dd]
                    + f1 * sBA[el][1*9 + n*3 + dd]
                    + f2 * sBA[el][2*9 + n*3 + dd];
            sT[el][j*3 + dd] = v;
        }
    }
    __syncthreads();

    // out[o][dd] = sum_j rp[o*48+j] * tmp[j][dd]
    const float4* rp4 = (const float4*)(RP + e * RPN + o * 48);
    float s0 = 0.f, s1 = 0.f, s2 = 0.f;
    const float* tp = sT[el];
#pragma unroll
    for (int q = 0; q < 12; q++) {
        float4 r = rp4[q];
        int j = q * 4;
        s0 = fmaf(r.x, tp[(j+0)*3+0], s0);
        s1 = fmaf(r.x, tp[(j+0)*3+1], s1);
        s2 = fmaf(r.x, tp[(j+0)*3+2], s2);
        s0 = fmaf(r.y, tp[(j+1)*3+0], s0);
        s1 = fmaf(r.y, tp[(j+1)*3+1], s1);
        s2 = fmaf(r.y, tp[(j+1)*3+2], s2);
        s0 = fmaf(r.z, tp[(j+2)*3+0], s0);
        s1 = fmaf(r.z, tp[(j+2)*3+1], s1);
        s2 = fmaf(r.z, tp[(j+2)*3+2], s2);
        s0 = fmaf(r.w, tp[(j+3)*3+0], s0);
        s1 = fmaf(r.w, tp[(j+3)*3+1], s1);
        s2 = fmaf(r.w, tp[(j+3)*3+2], s2);
    }
    float* op = out + (e * 16 + o) * 3;
    op[0] = s0; op[1] = s1; op[2] = s2;
}

// ---------------------------------------------------------------------------
extern "C" void kernel_launch(void* const* d_in, const int* in_sizes, int n_in,
                              void* d_out, int out_size)
{
    const float* edges = (const float*)d_in[0];
    const float* feats = (const float*)d_in[1];
    const float* basis = (const float*)d_in[2];
    const float* W1    = (const float*)d_in[3];
    const float* b1    = (const float*)d_in[4];
    const float* W2    = (const float*)d_in[5];
    const float* b2    = (const float*)d_in[6];
    const float* W3    = (const float*)d_in[7];
    float* out = (float*)d_out;

    float *H1, *H2, *RP;
    cudaGetSymbolAddress((void**)&H1, g_H1);
    cudaGetSymbolAddress((void**)&H2, g_H2);
    cudaGetSymbolAddress((void**)&RP, g_RP);

    dim3 blk(256);
    // layer 1: gelu(edges @ W1 + b1) -> H1
    mlp_gemm_kernel<32, true><<<dim3(E_TOTAL / 64, 1), blk>>>(
        edges, W1, 256, b1, H1, 256);
    // layer 2: gelu(H1 @ W2 + b2) -> H2
    mlp_gemm_kernel<256, true><<<dim3(E_TOTAL / 64, 1), blk>>>(
        H1, W2, 256, b2, H2, 256);
    // layer 3: H2 @ W3[:, 768:1536] -> RP (768 cols = 3 chunks of 256)
    mlp_gemm_kernel<256, false><<<dim3(E_TOTAL / 64, 3), blk>>>(
        H2, W3 + W3OFF, 1536, nullptr, RP, RPN);
    // tail contraction
    tail_kernel<<<E_TOTAL / 16, blk>>>(RP, feats, basis, out);
}

// round 3
// speedup vs baseline: 1.3433x; 1.3433x over previous
#include <cuda_runtime.h>
#include <cuda_bf16.h>
#include <math.h>
#include <stdint.h>

// Problem constants (fixed shapes)
#define E_TOTAL 65536     // B*N*K = 2*1024*32
#define MIDW    256
#define W3OFF   768       // SPLIT_OFF = 256*3
#define RPN     768       // SPLIT_SZ = NF*MI*MO = 3*16*16

// Scratch (device globals; no runtime allocation allowed)
__device__ float g_H1[E_TOTAL * MIDW];        //  64 MB
__device__ float g_H2[E_TOTAL * MIDW];        //  64 MB
__device__ float g_RP[(size_t)E_TOTAL * RPN]; // 201 MB

__device__ __forceinline__ float gelu_exact(float x) {
    return 0.5f * x * (1.0f + erff(x * 0.70710678118654752440f));
}

__device__ __forceinline__ uint32_t pack_bf2(__nv_bfloat16 a, __nv_bfloat16 b) {
    __nv_bfloat162 t;
    t.x = a; t.y = b;
    return *reinterpret_cast<uint32_t*>(&t);
}

// split f0,f1 into hi/lo bf16 pairs packed as b16x2 (low half = f0)
__device__ __forceinline__ void split2(float f0, float f1,
                                       uint32_t& hi, uint32_t& lo) {
    __nv_bfloat16 h0 = __float2bfloat16_rn(f0);
    __nv_bfloat16 h1 = __float2bfloat16_rn(f1);
    __nv_bfloat16 l0 = __float2bfloat16_rn(f0 - __bfloat162float(h0));
    __nv_bfloat16 l1 = __float2bfloat16_rn(f1 - __bfloat162float(h1));
    hi = pack_bf2(h0, h1);
    lo = pack_bf2(l0, l1);
}

__device__ __forceinline__ void mma_bf16(float* d, const uint32_t* a,
                                         const uint32_t* b) {
    asm volatile(
        "mma.sync.aligned.m16n8k16.row.col.f32.bf16.bf16.f32 "
        "{%0,%1,%2,%3}, {%4,%5,%6,%7}, {%8,%9}, {%0,%1,%2,%3};"
        : "+f"(d[0]), "+f"(d[1]), "+f"(d[2]), "+f"(d[3])
        : "r"(a[0]), "r"(a[1]), "r"(a[2]), "r"(a[3]),
          "r"(b[0]), "r"(b[1]));
}

// ---------------------------------------------------------------------------
// Tensor-core GEMM layer (split-bf16, fp32 accumulate):
//   C[row, cb*64 + n] = act( A[E, KTOT] @ B[KTOT, 64-chunk] (+ bias) )
// Block tile: 128 x 64 x 32. 256 threads = 8 warps in 4(m) x 2(n),
// each warp computes 32x32 via mma.m16n8k16 (2 m-frags x 4 n-frags).
// 3 MMAs per logical fp32 MMA: Ah*Bh + Ah*Bl + Al*Bh.
// smem: stride-20-word padded uint32 (bf16x2) tiles -> conflict-free LDS.
// ---------------------------------------------------------------------------
#define KP 20   // padded kpair stride (BK/2=16 + 4)

template<int KTOT, bool GELU>
__global__ __launch_bounds__(256, 2)
void mma_gemm_kernel(const float* __restrict__ A, const float* __restrict__ B,
                     int ldb, const float* __restrict__ bias,
                     float* __restrict__ C, int ldc)
{
    __shared__ uint32_t sAh[128 * KP];
    __shared__ uint32_t sAl[128 * KP];
    __shared__ uint32_t sBh[64 * KP];
    __shared__ uint32_t sBl[64 * KP];

    const int tid  = threadIdx.x;
    const int warp = tid >> 5;
    const int lane = tid & 31;
    const int wm   = warp >> 1;        // 0..3
    const int wn   = warp & 1;         // 0..1
    const int r    = lane >> 2;        // group id 0..7
    const int c    = lane & 3;         // 0..3
    const int row0 = blockIdx.x * 128;
    const int cb   = blockIdx.y;

    const float* Bc = B + (size_t)cb * 64;

    // A loader mapping: thread -> (m = tid/2, half-row seg = tid&1), 4 float4
    const int am  = tid >> 1;
    const int seg = tid & 1;
    const float* Arow = A + (size_t)(row0 + am) * KTOT + seg * 16;

    constexpr int NT = KTOT / 32;

    float acc[2][4][4];
#pragma unroll
    for (int i = 0; i < 2; i++)
#pragma unroll
        for (int j = 0; j < 4; j++)
#pragma unroll
            for (int q = 0; q < 4; q++) acc[i][j][q] = 0.f;

    float4 pav[4];
    float  pbv[4][2];

    // ---- prefetch tile 0 ----
#pragma unroll
    for (int i = 0; i < 4; i++)
        pav[i] = *(const float4*)(Arow + i * 4);
#pragma unroll
    for (int i = 0; i < 4; i++) {
        int idx = tid + i * 256;           // < 1024
        int n   = idx & 63;
        int k2  = idx >> 6;                // 0..15
        pbv[i][0] = Bc[(size_t)(2 * k2) * ldb + n];
        pbv[i][1] = Bc[(size_t)(2 * k2 + 1) * ldb + n];
    }

    // ---- store tile 0 ----
#pragma unroll
    for (int i = 0; i < 4; i++) {
        int k2 = seg * 8 + i * 2;
        uint32_t h0, l0, h1, l1;
        split2(pav[i].x, pav[i].y, h0, l0);
        split2(pav[i].z, pav[i].w, h1, l1);
        *(uint2*)&sAh[am * KP + k2] = make_uint2(h0, h1);
        *(uint2*)&sAl[am * KP + k2] = make_uint2(l0, l1);
    }
#pragma unroll
    for (int i = 0; i < 4; i++) {
        int idx = tid + i * 256;
        int n   = idx & 63;
        int k2  = idx >> 6;
        uint32_t h, l;
        split2(pbv[i][0], pbv[i][1], h, l);
        sBh[n * KP + k2] = h;
        sBl[n * KP + k2] = l;
    }
    __syncthreads();

#pragma unroll 1
    for (int kt = 0; kt < NT; kt++) {
        if (kt + 1 < NT) {
#pragma unroll
            for (int i = 0; i < 4; i++)
                pav[i] = *(const float4*)(Arow + (kt + 1) * 32 + i * 4);
#pragma unroll
            for (int i = 0; i < 4; i++) {
                int idx = tid + i * 256;
                int n   = idx & 63;
                int k2  = idx >> 6;
                pbv[i][0] = Bc[(size_t)((kt + 1) * 32 + 2 * k2) * ldb + n];
                pbv[i][1] = Bc[(size_t)((kt + 1) * 32 + 2 * k2 + 1) * ldb + n];
            }
        }

        // ---- compute: 2 k-steps of 16 ----
#pragma unroll
        for (int ks = 0; ks < 2; ks++) {
            const int kb = ks * 8 + c;
            uint32_t ah[2][4], al[2][4];
#pragma unroll
            for (int mi = 0; mi < 2; mi++) {
                int mrow = wm * 32 + mi * 16 + r;
                ah[mi][0] = sAh[mrow * KP + kb];
                ah[mi][1] = sAh[(mrow + 8) * KP + kb];
                ah[mi][2] = sAh[mrow * KP + kb + 4];
                ah[mi][3] = sAh[(mrow + 8) * KP + kb + 4];
                al[mi][0] = sAl[mrow * KP + kb];
                al[mi][1] = sAl[(mrow + 8) * KP + kb];
                al[mi][2] = sAl[mrow * KP + kb + 4];
                al[mi][3] = sAl[(mrow + 8) * KP + kb + 4];
            }
            uint32_t bh[4][2], bl[4][2];
#pragma unroll
            for (int nj = 0; nj < 4; nj++) {
                int ncol = wn * 32 + nj * 8 + r;
                bh[nj][0] = sBh[ncol * KP + kb];
                bh[nj][1] = sBh[ncol * KP + kb + 4];
                bl[nj][0] = sBl[ncol * KP + kb];
                bl[nj][1] = sBl[ncol * KP + kb + 4];
            }
#pragma unroll
            for (int mi = 0; mi < 2; mi++)
#pragma unroll
                for (int nj = 0; nj < 4; nj++) {
                    mma_bf16(acc[mi][nj], ah[mi], bh[nj]);
                    mma_bf16(acc[mi][nj], ah[mi], bl[nj]);
                    mma_bf16(acc[mi][nj], al[mi], bh[nj]);
                }
        }

        if (kt + 1 < NT) {
            __syncthreads();
#pragma unroll
            for (int i = 0; i < 4; i++) {
                int k2 = seg * 8 + i * 2;
                uint32_t h0, l0, h1, l1;
                split2(pav[i].x, pav[i].y, h0, l0);
                split2(pav[i].z, pav[i].w, h1, l1);
                *(uint2*)&sAh[am * KP + k2] = make_uint2(h0, h1);
                *(uint2*)&sAl[am * KP + k2] = make_uint2(l0, l1);
            }
#pragma unroll
            for (int i = 0; i < 4; i++) {
                int idx = tid + i * 256;
                int n   = idx & 63;
                int k2  = idx >> 6;
                uint32_t h, l;
                split2(pbv[i][0], pbv[i][1], h, l);
                sBh[n * KP + k2] = h;
                sBl[n * KP + k2] = l;
            }
            __syncthreads();
        }
    }

    // ---- epilogue ----
#pragma unroll
    for (int mi = 0; mi < 2; mi++) {
#pragma unroll
        for (int nj = 0; nj < 4; nj++) {
            int row = row0 + wm * 32 + mi * 16 + r;
            int col = cb * 64 + wn * 32 + nj * 8 + c * 2;
            float b0 = bias ? bias[col]     : 0.f;
            float b1 = bias ? bias[col + 1] : 0.f;
            float x0 = acc[mi][nj][0] + b0;
            float x1 = acc[mi][nj][1] + b1;
            float x2 = acc[mi][nj][2] + b0;
            float x3 = acc[mi][nj][3] + b1;
            if (GELU) {
                x0 = gelu_exact(x0); x1 = gelu_exact(x1);
                x2 = gelu_exact(x2); x3 = gelu_exact(x3);
            }
            *(float2*)&C[(size_t)row * ldc + col]       = make_float2(x0, x1);
            *(float2*)&C[(size_t)(row + 8) * ldc + col] = make_float2(x2, x3);
        }
    }
}

// ---------------------------------------------------------------------------
// Tail: per edge e,
//   tmp[j= i*3+n][dd] = sum_d f[i,d] * basis[d, n*3+dd]       (48 x 3)
//   out[o][dd]        = sum_j RP[e, o*48 + j] * tmp[j][dd]    (16 x 3)
// Block = 16 edges x 16 threads (one thread per (edge, o)).
// ---------------------------------------------------------------------------
__global__ __launch_bounds__(256)
void tail_kernel(const float* __restrict__ RP, const float* __restrict__ feats,
                 const float* __restrict__ basis, float* __restrict__ out)
{
    __shared__ float sT[16][145];
    __shared__ float sF[16][48];
    __shared__ float sBA[16][27];

    const int tid = threadIdx.x;
    const int el  = tid >> 4;
    const int o   = tid & 15;
    const size_t e = (size_t)blockIdx.x * 16 + el;

    const float* fe = feats + e * 48;
    sF[el][o*3+0] = fe[o*3+0];
    sF[el][o*3+1] = fe[o*3+1];
    sF[el][o*3+2] = fe[o*3+2];
    const float* be = basis + e * 27;
    for (int idx = o; idx < 27; idx += 16) sBA[el][idx] = be[idx];
    __syncthreads();

#pragma unroll
    for (int jj = 0; jj < 3; jj++) {
        int j = o + jj * 16;
        int i = j / 3, n = j - i * 3;
        float f0 = sF[el][i*3+0], f1 = sF[el][i*3+1], f2 = sF[el][i*3+2];
#pragma unroll
        for (int dd = 0; dd < 3; dd++) {
            sT[el][j*3 + dd] = f0 * sBA[el][n*3 + dd]
                             + f1 * sBA[el][9 + n*3 + dd]
                             + f2 * sBA[el][18 + n*3 + dd];
        }
    }
    __syncthreads();

    const float4* rp4 = (const float4*)(RP + e * RPN + o * 48);
    float s0 = 0.f, s1 = 0.f, s2 = 0.f;
    const float* tp = sT[el];
#pragma unroll
    for (int q = 0; q < 12; q++) {
        float4 rv = rp4[q];
        int j = q * 4;
        s0 = fmaf(rv.x, tp[(j+0)*3+0], s0);
        s1 = fmaf(rv.x, tp[(j+0)*3+1], s1);
        s2 = fmaf(rv.x, tp[(j+0)*3+2], s2);
        s0 = fmaf(rv.y, tp[(j+1)*3+0], s0);
        s1 = fmaf(rv.y, tp[(j+1)*3+1], s1);
        s2 = fmaf(rv.y, tp[(j+1)*3+2], s2);
        s0 = fmaf(rv.z, tp[(j+2)*3+0], s0);
        s1 = fmaf(rv.z, tp[(j+2)*3+1], s1);
        s2 = fmaf(rv.z, tp[(j+2)*3+2], s2);
        s0 = fmaf(rv.w, tp[(j+3)*3+0], s0);
        s1 = fmaf(rv.w, tp[(j+3)*3+1], s1);
        s2 = fmaf(rv.w, tp[(j+3)*3+2], s2);
    }
    float* op = out + (e * 16 + o) * 3;
    op[0] = s0; op[1] = s1; op[2] = s2;
}

// ---------------------------------------------------------------------------
extern "C" void kernel_launch(void* const* d_in, const int* in_sizes, int n_in,
                              void* d_out, int out_size)
{
    const float* edges = (const float*)d_in[0];
    const float* feats = (const float*)d_in[1];
    const float* basis = (const float*)d_in[2];
    const float* W1    = (const float*)d_in[3];
    const float* b1    = (const float*)d_in[4];
    const float* W2    = (const float*)d_in[5];
    const float* b2    = (const float*)d_in[6];
    const float* W3    = (const float*)d_in[7];
    float* out = (float*)d_out;

    float *H1, *H2, *RP;
    cudaGetSymbolAddress((void**)&H1, g_H1);
    cudaGetSymbolAddress((void**)&H2, g_H2);
    cudaGetSymbolAddress((void**)&RP, g_RP);

    dim3 blk(256);
    // layer 1: gelu(edges @ W1 + b1) -> H1   (256 cols = 4 chunks of 64)
    mma_gemm_kernel<32, true><<<dim3(E_TOTAL / 128, 4), blk>>>(
        edges, W1, 256, b1, H1, 256);
    // layer 2: gelu(H1 @ W2 + b2) -> H2
    mma_gemm_kernel<256, true><<<dim3(E_TOTAL / 128, 4), blk>>>(
        H1, W2, 256, b2, H2, 256);
    // layer 3: H2 @ W3[:, 768:1536] -> RP   (768 cols = 12 chunks of 64)
    mma_gemm_kernel<256, false><<<dim3(E_TOTAL / 128, 12), blk>>>(
        H2, W3 + W3OFF, 1536, nullptr, RP, RPN);
    // tail contraction
    tail_kernel<<<E_TOTAL / 16, blk>>>(RP, feats, basis, out);
}